// round 1
// baseline (speedup 1.0000x reference)
#include <cuda_runtime.h>
#include <math.h>

// Problem constants
#define T_LEN 512
#define B_SZ  64
#define I_SZ  512
#define H_SZ  1024
#define G3H   (3 * H_SZ)   // 3072
#define M_TOT (T_LEN * B_SZ) // 32768

// Scratch: x_gates (T*B*3H floats = 402 MB) + zero h0 (zero-initialized at load)
__device__ float g_gates[(size_t)M_TOT * G3H];
__device__ float g_h0[B_SZ * H_SZ];

// ---------------------------------------------------------------------------
// Kernel A: x_gates[m, n] = sum_k x[m,k] * w_ih[n,k] + b_ih[n]
// M=32768, N=3072, K=512.  64x64 tile, K-tile 16, 256 threads, 4x4 per thread.
// ---------------------------------------------------------------------------
__global__ __launch_bounds__(256)
void gemm_xgates(const float* __restrict__ A,   // x  (M, 512)
                 const float* __restrict__ W,   // w_ih (3072, 512)
                 const float* __restrict__ bias)
{
    __shared__ float As[16][68];
    __shared__ float Bs[16][68];

    const int m0 = blockIdx.y * 64;
    const int n0 = blockIdx.x * 64;
    const int tid = threadIdx.x;
    const int tm = tid >> 4;        // 0..15
    const int tn = tid & 15;        // 0..15
    const int lr = tid >> 2;        // 0..63 : row within tile for loading
    const int lk = (tid & 3) << 2;  // 0,4,8,12 : k offset (float4)

    float acc[4][4] = {};

    for (int k0 = 0; k0 < I_SZ; k0 += 16) {
        float4 a4 = *(const float4*)&A[(size_t)(m0 + lr) * I_SZ + k0 + lk];
        float4 b4 = *(const float4*)&W[(size_t)(n0 + lr) * I_SZ + k0 + lk];
        As[lk + 0][lr] = a4.x; As[lk + 1][lr] = a4.y;
        As[lk + 2][lr] = a4.z; As[lk + 3][lr] = a4.w;
        Bs[lk + 0][lr] = b4.x; Bs[lk + 1][lr] = b4.y;
        Bs[lk + 2][lr] = b4.z; Bs[lk + 3][lr] = b4.w;
        __syncthreads();

        #pragma unroll
        for (int kk = 0; kk < 16; kk++) {
            float4 ra = *(const float4*)&As[kk][tm << 2];
            float4 rb = *(const float4*)&Bs[kk][tn << 2];
            acc[0][0] += ra.x * rb.x; acc[0][1] += ra.x * rb.y;
            acc[0][2] += ra.x * rb.z; acc[0][3] += ra.x * rb.w;
            acc[1][0] += ra.y * rb.x; acc[1][1] += ra.y * rb.y;
            acc[1][2] += ra.y * rb.z; acc[1][3] += ra.y * rb.w;
            acc[2][0] += ra.z * rb.x; acc[2][1] += ra.z * rb.y;
            acc[2][2] += ra.z * rb.z; acc[2][3] += ra.z * rb.w;
            acc[3][0] += ra.w * rb.x; acc[3][1] += ra.w * rb.y;
            acc[3][2] += ra.w * rb.z; acc[3][3] += ra.w * rb.w;
        }
        __syncthreads();
    }

    const int nn = n0 + (tn << 2);
    float4 bv = *(const float4*)&bias[nn];
    #pragma unroll
    for (int i = 0; i < 4; i++) {
        float4 o;
        o.x = acc[i][0] + bv.x;
        o.y = acc[i][1] + bv.y;
        o.z = acc[i][2] + bv.z;
        o.w = acc[i][3] + bv.w;
        *(float4*)&g_gates[(size_t)(m0 + (tm << 2) + i) * G3H + nn] = o;
    }
}

// ---------------------------------------------------------------------------
// Kernel B: one GRU step.
//   hg = h_prev @ w_hh^T (+ b_hh) ; gates ; h_out = (1-z)*n + z*h_prev
// Tile: 16 batches x 32 j-columns x 3 gates per block. Grid (H/32=32, B/16=4).
// 256 threads; each thread: 2 batches (ty, ty+8) x 1 j-col x 3 gates.
// ---------------------------------------------------------------------------
__global__ __launch_bounds__(256)
void gru_step(int t,
              float* __restrict__ out_base,      // d_out: (T, B, H)
              const float* __restrict__ w_hh,    // (3072, 1024)
              const float* __restrict__ b_hh)    // (3072,)
{
    __shared__ float Hs[16][17];       // [kk][b]
    __shared__ float Ws[3][16][33];    // [gate][kk][j]

    const int tid = threadIdx.x;
    const int tx = tid & 31;           // j within tile
    const int ty = tid >> 5;           // 0..7
    const int j0 = blockIdx.x * 32;
    const int b0 = blockIdx.y * 16;

    const float* __restrict__ h_prev =
        (t == 0) ? g_h0 : (out_base + (size_t)(t - 1) * B_SZ * H_SZ);
    float* __restrict__ h_out = out_base + (size_t)t * B_SZ * H_SZ;
    const float* __restrict__ gates_t = g_gates + (size_t)t * B_SZ * G3H;

    float ar0 = 0.f, az0 = 0.f, an0 = 0.f;
    float ar1 = 0.f, az1 = 0.f, an1 = 0.f;

    const int hb = tid >> 4;       // 0..15 (batch for Hs load)
    const int hk = tid & 15;       // 0..15 (k for Hs load)
    const int widx = tid * 2;
    const int wj = widx >> 4;      // 0..31
    const int wk = widx & 15;      // even

    for (int k0 = 0; k0 < H_SZ; k0 += 16) {
        Hs[hk][hb] = h_prev[(size_t)(b0 + hb) * H_SZ + k0 + hk];
        #pragma unroll
        for (int g = 0; g < 3; g++) {
            float2 w2 = *(const float2*)&w_hh[(size_t)(g * H_SZ + j0 + wj) * H_SZ + k0 + wk];
            Ws[g][wk][wj]     = w2.x;
            Ws[g][wk + 1][wj] = w2.y;
        }
        __syncthreads();

        #pragma unroll
        for (int kk = 0; kk < 16; kk++) {
            float h0 = Hs[kk][ty];
            float h1 = Hs[kk][ty + 8];
            float wr = Ws[0][kk][tx];
            float wz = Ws[1][kk][tx];
            float wn = Ws[2][kk][tx];
            ar0 += h0 * wr; az0 += h0 * wz; an0 += h0 * wn;
            ar1 += h1 * wr; az1 += h1 * wz; an1 += h1 * wn;
        }
        __syncthreads();
    }

    const int j = j0 + tx;
    const float bhr = b_hh[j];
    const float bhz = b_hh[H_SZ + j];
    const float bhn = b_hh[2 * H_SZ + j];

    // batch b0+ty
    {
        const int b = b0 + ty;
        const float* xg = gates_t + (size_t)b * G3H;
        float r = 1.f / (1.f + expf(-(xg[j]            + ar0 + bhr)));
        float z = 1.f / (1.f + expf(-(xg[H_SZ + j]     + az0 + bhz)));
        float n = tanhf(xg[2 * H_SZ + j] + r * (an0 + bhn));
        float hp = h_prev[(size_t)b * H_SZ + j];
        h_out[(size_t)b * H_SZ + j] = (1.f - z) * n + z * hp;
    }
    // batch b0+ty+8
    {
        const int b = b0 + ty + 8;
        const float* xg = gates_t + (size_t)b * G3H;
        float r = 1.f / (1.f + expf(-(xg[j]            + ar1 + bhr)));
        float z = 1.f / (1.f + expf(-(xg[H_SZ + j]     + az1 + bhz)));
        float n = tanhf(xg[2 * H_SZ + j] + r * (an1 + bhn));
        float hp = h_prev[(size_t)b * H_SZ + j];
        h_out[(size_t)b * H_SZ + j] = (1.f - z) * n + z * hp;
    }
}

// Copy output[T-1] -> h_n slice of d_out
__global__ void copy_hn(const float* __restrict__ src, float* __restrict__ dst)
{
    int i = blockIdx.x * 256 + threadIdx.x;
    dst[i] = src[i];
}

extern "C" void kernel_launch(void* const* d_in, const int* in_sizes, int n_in,
                              void* d_out, int out_size)
{
    const float* x    = (const float*)d_in[0];   // (T, B, I)
    const float* w_ih = (const float*)d_in[1];   // (3H, I)
    const float* w_hh = (const float*)d_in[2];   // (3H, H)
    const float* b_ih = (const float*)d_in[3];   // (3H,)
    const float* b_hh = (const float*)d_in[4];   // (3H,)
    float* out = (float*)d_out;                  // (T*B*H) output, then (B*H) h_n

    // Phase 1: input projection GEMM
    dim3 gridA(G3H / 64, M_TOT / 64);
    gemm_xgates<<<gridA, 256>>>(x, w_ih, b_ih);

    // Phase 2: sequential recurrent scan
    dim3 gridS(H_SZ / 32, B_SZ / 16);
    for (int t = 0; t < T_LEN; t++) {
        gru_step<<<gridS, 256>>>(t, out, w_hh, b_hh);
    }

    // Phase 3: h_n = output[T-1]
    float* hn = out + (size_t)T_LEN * B_SZ * H_SZ;
    const float* last = out + (size_t)(T_LEN - 1) * B_SZ * H_SZ;
    copy_hn<<<(B_SZ * H_SZ) / 256, 256>>>(last, hn);
}

// round 2
// speedup vs baseline: 1.1300x; 1.1300x over previous
#include <cuda_runtime.h>
#include <math.h>

// Problem constants
#define T_LEN 512
#define B_SZ  64
#define I_SZ  512
#define H_SZ  1024
#define G3H   (3 * H_SZ)     // 3072
#define M_TOT (T_LEN * B_SZ) // 32768

typedef unsigned long long ull;

// Scratch: x_gates (T*B*3H floats = 402 MB) + zero h0 (zero-initialized at load)
__device__ float g_gates[(size_t)M_TOT * G3H];
__device__ float g_h0[B_SZ * H_SZ];

// ---------------------------------------------------------------------------
// f32x2 packed helpers (Blackwell FFMA2 — PTX-only)
// ---------------------------------------------------------------------------
__device__ __forceinline__ ull dup2(float w) {
    ull r; asm("mov.b64 %0, {%1, %1};" : "=l"(r) : "f"(w)); return r;
}
__device__ __forceinline__ void ffma2(ull& d, ull a, ull b) {
    asm("fma.rn.f32x2 %0, %1, %2, %0;" : "+l"(d) : "l"(a), "l"(b));
}
__device__ __forceinline__ void unpack2(ull v, float& lo, float& hi) {
    asm("mov.b64 {%0, %1}, %2;" : "=f"(lo), "=f"(hi) : "l"(v));
}

// ---------------------------------------------------------------------------
// Kernel A: x_gates[m, n] = sum_k x[m,k] * w_ih[n,k] + b_ih[n]
// M=32768, N=3072, K=512.  64x64 tile, K-tile 16, 256 threads.
// Thread tile 4m x 4n via f32x2 (2 m-pairs).
// ---------------------------------------------------------------------------
__global__ __launch_bounds__(256)
void gemm_xgates(const float* __restrict__ A,   // x  (M, 512)
                 const float* __restrict__ W,   // w_ih (3072, 512)
                 const float* __restrict__ bias)
{
    __shared__ __align__(16) float As[16][68];
    __shared__ __align__(16) float Bs2[16][68][2];   // n duplicated for f32x2

    const int m0 = blockIdx.y * 64;
    const int n0 = blockIdx.x * 64;
    const int tid = threadIdx.x;
    const int tm = tid >> 4;        // 0..15
    const int tn = tid & 15;        // 0..15
    const int lr = tid >> 2;        // 0..63 : row within tile for loading
    const int lk = (tid & 3) << 2;  // 0,4,8,12 : k offset (float4)

    ull acc2[2][4];                 // [m-pair][n]
    #pragma unroll
    for (int p = 0; p < 2; p++)
        #pragma unroll
        for (int n = 0; n < 4; n++) acc2[p][n] = 0ull;

    for (int k0 = 0; k0 < I_SZ; k0 += 16) {
        float4 a4 = *(const float4*)&A[(size_t)(m0 + lr) * I_SZ + k0 + lk];
        float4 b4 = *(const float4*)&W[(size_t)(n0 + lr) * I_SZ + k0 + lk];
        As[lk + 0][lr] = a4.x; As[lk + 1][lr] = a4.y;
        As[lk + 2][lr] = a4.z; As[lk + 3][lr] = a4.w;
        Bs2[lk + 0][lr][0] = b4.x; Bs2[lk + 0][lr][1] = b4.x;
        Bs2[lk + 1][lr][0] = b4.y; Bs2[lk + 1][lr][1] = b4.y;
        Bs2[lk + 2][lr][0] = b4.z; Bs2[lk + 2][lr][1] = b4.z;
        Bs2[lk + 3][lr][0] = b4.w; Bs2[lk + 3][lr][1] = b4.w;
        __syncthreads();

        #pragma unroll
        for (int kk = 0; kk < 16; kk++) {
            ull a01 = *(const ull*)&As[kk][tm << 2];
            ull a23 = *(const ull*)&As[kk][(tm << 2) + 2];
            ull w0  = *(const ull*)&Bs2[kk][(tn << 2) + 0][0];
            ull w1  = *(const ull*)&Bs2[kk][(tn << 2) + 1][0];
            ull w2  = *(const ull*)&Bs2[kk][(tn << 2) + 2][0];
            ull w3  = *(const ull*)&Bs2[kk][(tn << 2) + 3][0];
            ffma2(acc2[0][0], a01, w0); ffma2(acc2[0][1], a01, w1);
            ffma2(acc2[0][2], a01, w2); ffma2(acc2[0][3], a01, w3);
            ffma2(acc2[1][0], a23, w0); ffma2(acc2[1][1], a23, w1);
            ffma2(acc2[1][2], a23, w2); ffma2(acc2[1][3], a23, w3);
        }
        __syncthreads();
    }

    const int nn = n0 + (tn << 2);
    float4 bv = *(const float4*)&bias[nn];
    #pragma unroll
    for (int p = 0; p < 2; p++) {
        float lo0, hi0, lo1, hi1, lo2, hi2, lo3, hi3;
        unpack2(acc2[p][0], lo0, hi0);
        unpack2(acc2[p][1], lo1, hi1);
        unpack2(acc2[p][2], lo2, hi2);
        unpack2(acc2[p][3], lo3, hi3);
        float4 oL, oH;
        oL.x = lo0 + bv.x; oL.y = lo1 + bv.y; oL.z = lo2 + bv.z; oL.w = lo3 + bv.w;
        oH.x = hi0 + bv.x; oH.y = hi1 + bv.y; oH.z = hi2 + bv.z; oH.w = hi3 + bv.w;
        int row = m0 + (tm << 2) + 2 * p;
        *(float4*)&g_gates[(size_t)row       * G3H + nn] = oL;
        *(float4*)&g_gates[(size_t)(row + 1) * G3H + nn] = oH;
    }
}

// ---------------------------------------------------------------------------
// Kernel B: one GRU step, f32x2 version.
// Grid (128 j-tiles, 2 b-tiles) = 256 blocks.  Block = 128 threads = 4 warps.
// Each warp owns a K-slice of 256 (warp-private smem tiles, no block syncs
// in the mainloop).  Lane: j = lane&7, bg = lane>>3 (8 batches, 4 f32x2 pairs).
// Thread: 8 batches x 1 j x 3 gates = 12 f32x2 accumulators.
// Cross-warp K-reduction via smem, fused gate epilogue.
// ---------------------------------------------------------------------------
#define KT 16
__global__ __launch_bounds__(128)
void gru_step(int t,
              float* __restrict__ out_base,      // d_out: (T, B, H)
              const float* __restrict__ w_hh,    // (3072, 1024)
              const float* __restrict__ b_hh)    // (3072,)
{
    __shared__ __align__(16) float Hs[2][4][KT][32];        // [buf][warp][kk][b]
    __shared__ __align__(16) float Ws[2][4][KT][8][3][2];   // [buf][warp][kk][j][g][dup]
    __shared__ float Red[4][32][8][3];                      // [warp][b][j][g]

    const int tid  = threadIdx.x;
    const int s    = tid >> 5;          // warp = K slice (0..3)
    const int lane = tid & 31;
    const int j_l  = lane & 7;          // j within tile
    const int bg   = lane >> 3;         // batch group (0..3), 8 batches each

    const int j0 = blockIdx.x * 8;
    const int b0 = blockIdx.y * 32;
    const int kbeg = s * 256;

    const float* __restrict__ h_prev =
        (t == 0) ? g_h0 : (out_base + (size_t)(t - 1) * B_SZ * H_SZ);
    float* __restrict__ h_out = out_base + (size_t)t * B_SZ * H_SZ;
    const float* __restrict__ gates_t = g_gates + (size_t)t * B_SZ * G3H;

    // W-loader mapping: 96 float4 per tile / 32 lanes = 3 each
    // flat f: row = f>>2 (0..23: g = row/8, jj = row%8), kq = f&3
    ull acc[4][3];
    #pragma unroll
    for (int p = 0; p < 4; p++)
        #pragma unroll
        for (int g = 0; g < 3; g++) acc[p][g] = 0ull;

    float4 hreg[4];
    float4 wreg[3];
    int wrow[3], wkq[3];
    #pragma unroll
    for (int i = 0; i < 3; i++) {
        int f = lane + 32 * i;
        wrow[i] = f >> 2;
        wkq[i]  = f & 3;
    }

    // prefetch tile 0
    {
        const int k0 = kbeg;
        const float* hp = &h_prev[(size_t)(b0 + lane) * H_SZ + k0];
        #pragma unroll
        for (int i = 0; i < 4; i++) hreg[i] = *(const float4*)&hp[4 * i];
        #pragma unroll
        for (int i = 0; i < 3; i++) {
            int g = wrow[i] >> 3, jj = wrow[i] & 7;
            wreg[i] = *(const float4*)&w_hh[(size_t)(g * H_SZ + j0 + jj) * H_SZ + k0 + 4 * wkq[i]];
        }
    }
    // store tile 0 into buf 0
    #pragma unroll
    for (int i = 0; i < 4; i++) {
        Hs[0][s][4 * i + 0][lane] = hreg[i].x;
        Hs[0][s][4 * i + 1][lane] = hreg[i].y;
        Hs[0][s][4 * i + 2][lane] = hreg[i].z;
        Hs[0][s][4 * i + 3][lane] = hreg[i].w;
    }
    #pragma unroll
    for (int i = 0; i < 3; i++) {
        int g = wrow[i] >> 3, jj = wrow[i] & 7;
        int kk = 4 * wkq[i];
        *(ull*)&Ws[0][s][kk + 0][jj][g][0] = dup2(wreg[i].x);
        *(ull*)&Ws[0][s][kk + 1][jj][g][0] = dup2(wreg[i].y);
        *(ull*)&Ws[0][s][kk + 2][jj][g][0] = dup2(wreg[i].z);
        *(ull*)&Ws[0][s][kk + 3][jj][g][0] = dup2(wreg[i].w);
    }
    __syncwarp();

    #pragma unroll 1
    for (int tile = 0; tile < 16; tile++) {
        const int buf = tile & 1;
        // prefetch next tile (global -> regs)
        if (tile < 15) {
            const int k0 = kbeg + (tile + 1) * KT;
            const float* hp = &h_prev[(size_t)(b0 + lane) * H_SZ + k0];
            #pragma unroll
            for (int i = 0; i < 4; i++) hreg[i] = *(const float4*)&hp[4 * i];
            #pragma unroll
            for (int i = 0; i < 3; i++) {
                int g = wrow[i] >> 3, jj = wrow[i] & 7;
                wreg[i] = *(const float4*)&w_hh[(size_t)(g * H_SZ + j0 + jj) * H_SZ + k0 + 4 * wkq[i]];
            }
        }
        // compute current buffer
        #pragma unroll
        for (int kk = 0; kk < KT; kk++) {
            float4 h03 = *(const float4*)&Hs[buf][s][kk][bg * 8];
            float4 h47 = *(const float4*)&Hs[buf][s][kk][bg * 8 + 4];
            ull hp0, hp1, hp2, hp3;
            asm("mov.b64 %0, {%1, %2};" : "=l"(hp0) : "f"(h03.x), "f"(h03.y));
            asm("mov.b64 %0, {%1, %2};" : "=l"(hp1) : "f"(h03.z), "f"(h03.w));
            asm("mov.b64 %0, {%1, %2};" : "=l"(hp2) : "f"(h47.x), "f"(h47.y));
            asm("mov.b64 %0, {%1, %2};" : "=l"(hp3) : "f"(h47.z), "f"(h47.w));
            ull wr = *(const ull*)&Ws[buf][s][kk][j_l][0][0];
            ull wz = *(const ull*)&Ws[buf][s][kk][j_l][1][0];
            ull wn = *(const ull*)&Ws[buf][s][kk][j_l][2][0];
            ffma2(acc[0][0], hp0, wr); ffma2(acc[0][1], hp0, wz); ffma2(acc[0][2], hp0, wn);
            ffma2(acc[1][0], hp1, wr); ffma2(acc[1][1], hp1, wz); ffma2(acc[1][2], hp1, wn);
            ffma2(acc[2][0], hp2, wr); ffma2(acc[2][1], hp2, wz); ffma2(acc[2][2], hp2, wn);
            ffma2(acc[3][0], hp3, wr); ffma2(acc[3][1], hp3, wz); ffma2(acc[3][2], hp3, wn);
        }
        // store next tile (regs -> other buffer)
        if (tile < 15) {
            const int nbuf = buf ^ 1;
            __syncwarp();
            #pragma unroll
            for (int i = 0; i < 4; i++) {
                Hs[nbuf][s][4 * i + 0][lane] = hreg[i].x;
                Hs[nbuf][s][4 * i + 1][lane] = hreg[i].y;
                Hs[nbuf][s][4 * i + 2][lane] = hreg[i].z;
                Hs[nbuf][s][4 * i + 3][lane] = hreg[i].w;
            }
            #pragma unroll
            for (int i = 0; i < 3; i++) {
                int g = wrow[i] >> 3, jj = wrow[i] & 7;
                int kk = 4 * wkq[i];
                *(ull*)&Ws[nbuf][s][kk + 0][jj][g][0] = dup2(wreg[i].x);
                *(ull*)&Ws[nbuf][s][kk + 1][jj][g][0] = dup2(wreg[i].y);
                *(ull*)&Ws[nbuf][s][kk + 2][jj][g][0] = dup2(wreg[i].z);
                *(ull*)&Ws[nbuf][s][kk + 3][jj][g][0] = dup2(wreg[i].w);
            }
            __syncwarp();
        }
    }

    // dump partials: acc[p][g] covers batches bg*8 + 2p (lo), +2p+1 (hi)
    #pragma unroll
    for (int p = 0; p < 4; p++) {
        #pragma unroll
        for (int g = 0; g < 3; g++) {
            float lo, hi;
            unpack2(acc[p][g], lo, hi);
            Red[s][bg * 8 + 2 * p + 0][j_l][g] = lo;
            Red[s][bg * 8 + 2 * p + 1][j_l][g] = hi;
        }
    }
    __syncthreads();

    // epilogue: 256 outputs (32 b x 8 j), 2 per thread
    #pragma unroll
    for (int e = 0; e < 2; e++) {
        int o   = tid + e * 128;
        int b_l = o >> 3;
        int jj  = o & 7;
        float sr = 0.f, sz = 0.f, sn = 0.f;
        #pragma unroll
        for (int w = 0; w < 4; w++) {
            sr += Red[w][b_l][jj][0];
            sz += Red[w][b_l][jj][1];
            sn += Red[w][b_l][jj][2];
        }
        int j = j0 + jj;
        int b = b0 + b_l;
        const float* xg = gates_t + (size_t)b * G3H;
        float r = 1.f / (1.f + expf(-(xg[j]              + sr + b_hh[j])));
        float z = 1.f / (1.f + expf(-(xg[H_SZ + j]       + sz + b_hh[H_SZ + j])));
        float n = tanhf(xg[2 * H_SZ + j] + r * (sn + b_hh[2 * H_SZ + j]));
        float hp = h_prev[(size_t)b * H_SZ + j];
        h_out[(size_t)b * H_SZ + j] = (1.f - z) * n + z * hp;
    }
}

// Copy output[T-1] -> h_n slice of d_out
__global__ void copy_hn(const float* __restrict__ src, float* __restrict__ dst)
{
    int i = blockIdx.x * 256 + threadIdx.x;
    dst[i] = src[i];
}

extern "C" void kernel_launch(void* const* d_in, const int* in_sizes, int n_in,
                              void* d_out, int out_size)
{
    const float* x    = (const float*)d_in[0];   // (T, B, I)
    const float* w_ih = (const float*)d_in[1];   // (3H, I)
    const float* w_hh = (const float*)d_in[2];   // (3H, H)
    const float* b_ih = (const float*)d_in[3];   // (3H,)
    const float* b_hh = (const float*)d_in[4];   // (3H,)
    float* out = (float*)d_out;                  // (T*B*H) output, then (B*H) h_n

    // Phase 1: input projection GEMM
    dim3 gridA(G3H / 64, M_TOT / 64);
    gemm_xgates<<<gridA, 256>>>(x, w_ih, b_ih);

    // Phase 2: sequential recurrent scan
    dim3 gridS(H_SZ / 8, B_SZ / 32);   // (128, 2) = 256 blocks
    for (int t = 0; t < T_LEN; t++) {
        gru_step<<<gridS, 128>>>(t, out, w_hh, b_hh);
    }

    // Phase 3: h_n = output[T-1]
    float* hn = out + (size_t)T_LEN * B_SZ * H_SZ;
    const float* last = out + (size_t)(T_LEN - 1) * B_SZ * H_SZ;
    copy_hn<<<(B_SZ * H_SZ) / 256, 256>>>(last, hn);
}

// round 3
// speedup vs baseline: 1.1305x; 1.0005x over previous
#include <cuda_runtime.h>
#include <math.h>

// Problem constants
#define T_LEN 512
#define B_SZ  64
#define I_SZ  512
#define H_SZ  1024
#define G3H   (3 * H_SZ)     // 3072
#define M_TOT (T_LEN * B_SZ) // 32768

typedef unsigned long long ull;

// Scratch: x_gates (T*B*3H floats = 402 MB) + zero h0 (zero-initialized at load)
__device__ float g_gates[(size_t)M_TOT * G3H];
__device__ float g_h0[B_SZ * H_SZ];

// ---------------------------------------------------------------------------
// f32x2 packed helpers (Blackwell FFMA2 — PTX-only)
// ---------------------------------------------------------------------------
__device__ __forceinline__ ull dup2(float w) {
    ull r; asm("mov.b64 %0, {%1, %1};" : "=l"(r) : "f"(w)); return r;
}
__device__ __forceinline__ void ffma2(ull& d, ull a, ull b) {
    asm("fma.rn.f32x2 %0, %1, %2, %0;" : "+l"(d) : "l"(a), "l"(b));
}
__device__ __forceinline__ void unpack2(ull v, float& lo, float& hi) {
    asm("mov.b64 {%0, %1}, %2;" : "=f"(lo), "=f"(hi) : "l"(v));
}

// ---------------------------------------------------------------------------
// Kernel A: x_gates[m, n] = sum_k x[m,k] * w_ih[n,k] + b_ih[n]
// M=32768, N=3072, K=512.  64x64 tile, K-tile 16, 256 threads.
// Thread tile 4m x 4n via f32x2 (2 m-pairs).
// ---------------------------------------------------------------------------
__global__ __launch_bounds__(256)
void gemm_xgates(const float* __restrict__ A,   // x  (M, 512)
                 const float* __restrict__ W,   // w_ih (3072, 512)
                 const float* __restrict__ bias)
{
    __shared__ __align__(16) float As[16][68];
    __shared__ __align__(16) float Bs2[16][68][2];   // n duplicated for f32x2

    const int m0 = blockIdx.y * 64;
    const int n0 = blockIdx.x * 64;
    const int tid = threadIdx.x;
    const int tm = tid >> 4;        // 0..15
    const int tn = tid & 15;        // 0..15
    const int lr = tid >> 2;        // 0..63 : row within tile for loading
    const int lk = (tid & 3) << 2;  // 0,4,8,12 : k offset (float4)

    ull acc2[2][4];                 // [m-pair][n]
    #pragma unroll
    for (int p = 0; p < 2; p++)
        #pragma unroll
        for (int n = 0; n < 4; n++) acc2[p][n] = 0ull;

    for (int k0 = 0; k0 < I_SZ; k0 += 16) {
        float4 a4 = *(const float4*)&A[(size_t)(m0 + lr) * I_SZ + k0 + lk];
        float4 b4 = *(const float4*)&W[(size_t)(n0 + lr) * I_SZ + k0 + lk];
        As[lk + 0][lr] = a4.x; As[lk + 1][lr] = a4.y;
        As[lk + 2][lr] = a4.z; As[lk + 3][lr] = a4.w;
        Bs2[lk + 0][lr][0] = b4.x; Bs2[lk + 0][lr][1] = b4.x;
        Bs2[lk + 1][lr][0] = b4.y; Bs2[lk + 1][lr][1] = b4.y;
        Bs2[lk + 2][lr][0] = b4.z; Bs2[lk + 2][lr][1] = b4.z;
        Bs2[lk + 3][lr][0] = b4.w; Bs2[lk + 3][lr][1] = b4.w;
        __syncthreads();

        #pragma unroll
        for (int kk = 0; kk < 16; kk++) {
            ull a01 = *(const ull*)&As[kk][tm << 2];
            ull a23 = *(const ull*)&As[kk][(tm << 2) + 2];
            ull w0  = *(const ull*)&Bs2[kk][(tn << 2) + 0][0];
            ull w1  = *(const ull*)&Bs2[kk][(tn << 2) + 1][0];
            ull w2  = *(const ull*)&Bs2[kk][(tn << 2) + 2][0];
            ull w3  = *(const ull*)&Bs2[kk][(tn << 2) + 3][0];
            ffma2(acc2[0][0], a01, w0); ffma2(acc2[0][1], a01, w1);
            ffma2(acc2[0][2], a01, w2); ffma2(acc2[0][3], a01, w3);
            ffma2(acc2[1][0], a23, w0); ffma2(acc2[1][1], a23, w1);
            ffma2(acc2[1][2], a23, w2); ffma2(acc2[1][3], a23, w3);
        }
        __syncthreads();
    }

    const int nn = n0 + (tn << 2);
    float4 bv = *(const float4*)&bias[nn];
    #pragma unroll
    for (int p = 0; p < 2; p++) {
        float lo0, hi0, lo1, hi1, lo2, hi2, lo3, hi3;
        unpack2(acc2[p][0], lo0, hi0);
        unpack2(acc2[p][1], lo1, hi1);
        unpack2(acc2[p][2], lo2, hi2);
        unpack2(acc2[p][3], lo3, hi3);
        float4 oL, oH;
        oL.x = lo0 + bv.x; oL.y = lo1 + bv.y; oL.z = lo2 + bv.z; oL.w = lo3 + bv.w;
        oH.x = hi0 + bv.x; oH.y = hi1 + bv.y; oH.z = hi2 + bv.z; oH.w = hi3 + bv.w;
        int row = m0 + (tm << 2) + 2 * p;
        *(float4*)&g_gates[(size_t)row       * G3H + nn] = oL;
        *(float4*)&g_gates[(size_t)(row + 1) * G3H + nn] = oH;
    }
}

// ---------------------------------------------------------------------------
// Kernel B: one GRU step, f32x2 version.
// Grid (128 j-tiles, 2 b-tiles) = 256 blocks.  Block = 128 threads = 4 warps.
// Each warp owns a K-slice of 256 (warp-private smem tiles, no block syncs
// in the mainloop).  Lane: j = lane&7, bg = lane>>3 (8 batches, 4 f32x2 pairs).
// Thread: 8 batches x 1 j x 3 gates = 12 f32x2 accumulators.
// Cross-warp K-reduction via smem, fused gate epilogue.
// ---------------------------------------------------------------------------
#define KT 16
__global__ __launch_bounds__(128)
void gru_step(int t,
              float* __restrict__ out_base,      // d_out: (T, B, H)
              const float* __restrict__ w_hh,    // (3072, 1024)
              const float* __restrict__ b_hh)    // (3072,)
{
    __shared__ __align__(16) float Hs[2][4][KT][32];        // [buf][warp][kk][b]
    __shared__ __align__(16) float Ws[2][4][KT][8][3][2];   // [buf][warp][kk][j][g][dup]
    __shared__ float Red[4][32][8][3];                      // [warp][b][j][g]

    const int tid  = threadIdx.x;
    const int s    = tid >> 5;          // warp = K slice (0..3)
    const int lane = tid & 31;
    const int j_l  = lane & 7;          // j within tile
    const int bg   = lane >> 3;         // batch group (0..3), 8 batches each

    const int j0 = blockIdx.x * 8;
    const int b0 = blockIdx.y * 32;
    const int kbeg = s * 256;

    const float* __restrict__ h_prev =
        (t == 0) ? g_h0 : (out_base + (size_t)(t - 1) * B_SZ * H_SZ);
    float* __restrict__ h_out = out_base + (size_t)t * B_SZ * H_SZ;
    const float* __restrict__ gates_t = g_gates + (size_t)t * B_SZ * G3H;

    // W-loader mapping: 96 float4 per tile / 32 lanes = 3 each
    // flat f: row = f>>2 (0..23: g = row/8, jj = row%8), kq = f&3
    ull acc[4][3];
    #pragma unroll
    for (int p = 0; p < 4; p++)
        #pragma unroll
        for (int g = 0; g < 3; g++) acc[p][g] = 0ull;

    float4 hreg[4];
    float4 wreg[3];
    int wrow[3], wkq[3];
    #pragma unroll
    for (int i = 0; i < 3; i++) {
        int f = lane + 32 * i;
        wrow[i] = f >> 2;
        wkq[i]  = f & 3;
    }

    // prefetch tile 0
    {
        const int k0 = kbeg;
        const float* hp = &h_prev[(size_t)(b0 + lane) * H_SZ + k0];
        #pragma unroll
        for (int i = 0; i < 4; i++) hreg[i] = *(const float4*)&hp[4 * i];
        #pragma unroll
        for (int i = 0; i < 3; i++) {
            int g = wrow[i] >> 3, jj = wrow[i] & 7;
            wreg[i] = *(const float4*)&w_hh[(size_t)(g * H_SZ + j0 + jj) * H_SZ + k0 + 4 * wkq[i]];
        }
    }
    // store tile 0 into buf 0
    #pragma unroll
    for (int i = 0; i < 4; i++) {
        Hs[0][s][4 * i + 0][lane] = hreg[i].x;
        Hs[0][s][4 * i + 1][lane] = hreg[i].y;
        Hs[0][s][4 * i + 2][lane] = hreg[i].z;
        Hs[0][s][4 * i + 3][lane] = hreg[i].w;
    }
    #pragma unroll
    for (int i = 0; i < 3; i++) {
        int g = wrow[i] >> 3, jj = wrow[i] & 7;
        int kk = 4 * wkq[i];
        *(ull*)&Ws[0][s][kk + 0][jj][g][0] = dup2(wreg[i].x);
        *(ull*)&Ws[0][s][kk + 1][jj][g][0] = dup2(wreg[i].y);
        *(ull*)&Ws[0][s][kk + 2][jj][g][0] = dup2(wreg[i].z);
        *(ull*)&Ws[0][s][kk + 3][jj][g][0] = dup2(wreg[i].w);
    }
    __syncwarp();

    #pragma unroll 1
    for (int tile = 0; tile < 16; tile++) {
        const int buf = tile & 1;
        // prefetch next tile (global -> regs)
        if (tile < 15) {
            const int k0 = kbeg + (tile + 1) * KT;
            const float* hp = &h_prev[(size_t)(b0 + lane) * H_SZ + k0];
            #pragma unroll
            for (int i = 0; i < 4; i++) hreg[i] = *(const float4*)&hp[4 * i];
            #pragma unroll
            for (int i = 0; i < 3; i++) {
                int g = wrow[i] >> 3, jj = wrow[i] & 7;
                wreg[i] = *(const float4*)&w_hh[(size_t)(g * H_SZ + j0 + jj) * H_SZ + k0 + 4 * wkq[i]];
            }
        }
        // compute current buffer
        #pragma unroll
        for (int kk = 0; kk < KT; kk++) {
            float4 h03 = *(const float4*)&Hs[buf][s][kk][bg * 8];
            float4 h47 = *(const float4*)&Hs[buf][s][kk][bg * 8 + 4];
            ull hp0, hp1, hp2, hp3;
            asm("mov.b64 %0, {%1, %2};" : "=l"(hp0) : "f"(h03.x), "f"(h03.y));
            asm("mov.b64 %0, {%1, %2};" : "=l"(hp1) : "f"(h03.z), "f"(h03.w));
            asm("mov.b64 %0, {%1, %2};" : "=l"(hp2) : "f"(h47.x), "f"(h47.y));
            asm("mov.b64 %0, {%1, %2};" : "=l"(hp3) : "f"(h47.z), "f"(h47.w));
            ull wr = *(const ull*)&Ws[buf][s][kk][j_l][0][0];
            ull wz = *(const ull*)&Ws[buf][s][kk][j_l][1][0];
            ull wn = *(const ull*)&Ws[buf][s][kk][j_l][2][0];
            ffma2(acc[0][0], hp0, wr); ffma2(acc[0][1], hp0, wz); ffma2(acc[0][2], hp0, wn);
            ffma2(acc[1][0], hp1, wr); ffma2(acc[1][1], hp1, wz); ffma2(acc[1][2], hp1, wn);
            ffma2(acc[2][0], hp2, wr); ffma2(acc[2][1], hp2, wz); ffma2(acc[2][2], hp2, wn);
            ffma2(acc[3][0], hp3, wr); ffma2(acc[3][1], hp3, wz); ffma2(acc[3][2], hp3, wn);
        }
        // store next tile (regs -> other buffer)
        if (tile < 15) {
            const int nbuf = buf ^ 1;
            __syncwarp();
            #pragma unroll
            for (int i = 0; i < 4; i++) {
                Hs[nbuf][s][4 * i + 0][lane] = hreg[i].x;
                Hs[nbuf][s][4 * i + 1][lane] = hreg[i].y;
                Hs[nbuf][s][4 * i + 2][lane] = hreg[i].z;
                Hs[nbuf][s][4 * i + 3][lane] = hreg[i].w;
            }
            #pragma unroll
            for (int i = 0; i < 3; i++) {
                int g = wrow[i] >> 3, jj = wrow[i] & 7;
                int kk = 4 * wkq[i];
                *(ull*)&Ws[nbuf][s][kk + 0][jj][g][0] = dup2(wreg[i].x);
                *(ull*)&Ws[nbuf][s][kk + 1][jj][g][0] = dup2(wreg[i].y);
                *(ull*)&Ws[nbuf][s][kk + 2][jj][g][0] = dup2(wreg[i].z);
                *(ull*)&Ws[nbuf][s][kk + 3][jj][g][0] = dup2(wreg[i].w);
            }
            __syncwarp();
        }
    }

    // dump partials: acc[p][g] covers batches bg*8 + 2p (lo), +2p+1 (hi)
    #pragma unroll
    for (int p = 0; p < 4; p++) {
        #pragma unroll
        for (int g = 0; g < 3; g++) {
            float lo, hi;
            unpack2(acc[p][g], lo, hi);
            Red[s][bg * 8 + 2 * p + 0][j_l][g] = lo;
            Red[s][bg * 8 + 2 * p + 1][j_l][g] = hi;
        }
    }
    __syncthreads();

    // epilogue: 256 outputs (32 b x 8 j), 2 per thread
    #pragma unroll
    for (int e = 0; e < 2; e++) {
        int o   = tid + e * 128;
        int b_l = o >> 3;
        int jj  = o & 7;
        float sr = 0.f, sz = 0.f, sn = 0.f;
        #pragma unroll
        for (int w = 0; w < 4; w++) {
            sr += Red[w][b_l][jj][0];
            sz += Red[w][b_l][jj][1];
            sn += Red[w][b_l][jj][2];
        }
        int j = j0 + jj;
        int b = b0 + b_l;
        const float* xg = gates_t + (size_t)b * G3H;
        float r = 1.f / (1.f + expf(-(xg[j]              + sr + b_hh[j])));
        float z = 1.f / (1.f + expf(-(xg[H_SZ + j]       + sz + b_hh[H_SZ + j])));
        float n = tanhf(xg[2 * H_SZ + j] + r * (sn + b_hh[2 * H_SZ + j]));
        float hp = h_prev[(size_t)b * H_SZ + j];
        h_out[(size_t)b * H_SZ + j] = (1.f - z) * n + z * hp;
    }
}

// Copy output[T-1] -> h_n slice of d_out
__global__ void copy_hn(const float* __restrict__ src, float* __restrict__ dst)
{
    int i = blockIdx.x * 256 + threadIdx.x;
    dst[i] = src[i];
}

extern "C" void kernel_launch(void* const* d_in, const int* in_sizes, int n_in,
                              void* d_out, int out_size)
{
    const float* x    = (const float*)d_in[0];   // (T, B, I)
    const float* w_ih = (const float*)d_in[1];   // (3H, I)
    const float* w_hh = (const float*)d_in[2];   // (3H, H)
    const float* b_ih = (const float*)d_in[3];   // (3H,)
    const float* b_hh = (const float*)d_in[4];   // (3H,)
    float* out = (float*)d_out;                  // (T*B*H) output, then (B*H) h_n

    // Phase 1: input projection GEMM
    dim3 gridA(G3H / 64, M_TOT / 64);
    gemm_xgates<<<gridA, 256>>>(x, w_ih, b_ih);

    // Phase 2: sequential recurrent scan
    dim3 gridS(H_SZ / 8, B_SZ / 32);   // (128, 2) = 256 blocks
    for (int t = 0; t < T_LEN; t++) {
        gru_step<<<gridS, 128>>>(t, out, w_hh, b_hh);
    }

    // Phase 3: h_n = output[T-1]
    float* hn = out + (size_t)T_LEN * B_SZ * H_SZ;
    const float* last = out + (size_t)(T_LEN - 1) * B_SZ * H_SZ;
    copy_hn<<<(B_SZ * H_SZ) / 256, 256>>>(last, hn);
}

// round 5
// speedup vs baseline: 2.2718x; 2.0095x over previous
#include <cuda_runtime.h>
#include <math.h>

// Problem constants
#define T_LEN 512
#define B_SZ  64
#define I_SZ  512
#define H_SZ  1024
#define G3H   3072
#define M_TOT 32768          // T*B

#define NBLK  128            // persistent blocks (1 per SM, <=148)
#define JT    8              // hidden units per block
#define NROW  24             // gate rows per block (3*JT)
#define HS    34             // h chunk inner stride (EVEN: 8B-aligned ull reads)
#define REDS  66             // Red row stride

typedef unsigned long long ull;

__device__ __align__(16) float g_gates[(size_t)M_TOT * G3H];
__device__ __align__(16) float g_h0[B_SZ * H_SZ];  // zero-init, never written
__device__ unsigned g_sync;

// ---------------------------------------------------------------------------
// f32x2 helpers
// ---------------------------------------------------------------------------
__device__ __forceinline__ ull dup2(float w) {
    ull r; asm("mov.b64 %0, {%1, %1};" : "=l"(r) : "f"(w)); return r;
}
__device__ __forceinline__ void ffma2(ull& d, ull a, ull b) {
    asm("fma.rn.f32x2 %0, %1, %2, %0;" : "+l"(d) : "l"(a), "l"(b));
}
__device__ __forceinline__ float sum2(ull v) {
    float lo, hi;
    asm("mov.b64 {%0, %1}, %2;" : "=f"(lo), "=f"(hi) : "l"(v));
    return lo + hi;
}
__device__ __forceinline__ void unpack2(ull v, float& lo, float& hi) {
    asm("mov.b64 {%0, %1}, %2;" : "=f"(lo), "=f"(hi) : "l"(v));
}

// ---------------------------------------------------------------------------
// Kernel A: x_gates = x @ w_ih^T + b_ih.  M=32768, N=3072, K=512.
// 128x64 tile, K-tile 16, 256 threads, thread tile 8m x 4n via f32x2 (m-pairs).
// ---------------------------------------------------------------------------
__global__ __launch_bounds__(256)
void gemm_xgates(const float* __restrict__ A,
                 const float* __restrict__ W,
                 const float* __restrict__ bias)
{
    __shared__ __align__(16) float As[16][132];
    __shared__ __align__(16) float Bs[16][68];

    const int m0 = blockIdx.y * 128;
    const int n0 = blockIdx.x * 64;
    const int tid = threadIdx.x;
    const int tm = tid >> 4;          // 0..15 -> rows tm*8..+7
    const int tn = tid & 15;          // 0..15 -> cols tn*4..+3
    const int alr = tid >> 1;         // 0..127
    const int alk = (tid & 1) * 8;    // 0 or 8
    const int wlr = tid >> 2;         // 0..63
    const int wlk = (tid & 3) * 4;    // 0,4,8,12

    ull acc[4][4];
    #pragma unroll
    for (int p = 0; p < 4; p++)
        #pragma unroll
        for (int n = 0; n < 4; n++) acc[p][n] = 0ull;

    for (int k0 = 0; k0 < I_SZ; k0 += 16) {
        float4 a0 = *(const float4*)&A[(size_t)(m0 + alr) * I_SZ + k0 + alk];
        float4 a1 = *(const float4*)&A[(size_t)(m0 + alr) * I_SZ + k0 + alk + 4];
        float4 b0 = *(const float4*)&W[(size_t)(n0 + wlr) * I_SZ + k0 + wlk];
        As[alk + 0][alr] = a0.x; As[alk + 1][alr] = a0.y;
        As[alk + 2][alr] = a0.z; As[alk + 3][alr] = a0.w;
        As[alk + 4][alr] = a1.x; As[alk + 5][alr] = a1.y;
        As[alk + 6][alr] = a1.z; As[alk + 7][alr] = a1.w;
        Bs[wlk + 0][wlr] = b0.x; Bs[wlk + 1][wlr] = b0.y;
        Bs[wlk + 2][wlr] = b0.z; Bs[wlk + 3][wlr] = b0.w;
        __syncthreads();

        #pragma unroll
        for (int kk = 0; kk < 16; kk++) {
            ull am[4];
            #pragma unroll
            for (int p = 0; p < 4; p++)
                am[p] = *(const ull*)&As[kk][tm * 8 + 2 * p];
            ull wd[4];
            #pragma unroll
            for (int n = 0; n < 4; n++)
                wd[n] = dup2(Bs[kk][tn * 4 + n]);
            #pragma unroll
            for (int p = 0; p < 4; p++) {
                ffma2(acc[p][0], am[p], wd[0]);
                ffma2(acc[p][1], am[p], wd[1]);
                ffma2(acc[p][2], am[p], wd[2]);
                ffma2(acc[p][3], am[p], wd[3]);
            }
        }
        __syncthreads();
    }

    const int nn = n0 + tn * 4;
    float4 bv = *(const float4*)&bias[nn];
    #pragma unroll
    for (int p = 0; p < 4; p++) {
        float lo0, hi0, lo1, hi1, lo2, hi2, lo3, hi3;
        unpack2(acc[p][0], lo0, hi0);
        unpack2(acc[p][1], lo1, hi1);
        unpack2(acc[p][2], lo2, hi2);
        unpack2(acc[p][3], lo3, hi3);
        float4 oL, oH;
        oL.x = lo0 + bv.x; oL.y = lo1 + bv.y; oL.z = lo2 + bv.z; oL.w = lo3 + bv.w;
        oH.x = hi0 + bv.x; oH.y = hi1 + bv.y; oH.z = hi2 + bv.z; oH.w = hi3 + bv.w;
        int row = m0 + tm * 8 + 2 * p;
        *(float4*)&g_gates[(size_t)row       * G3H + nn] = oL;
        *(float4*)&g_gates[(size_t)(row + 1) * G3H + nn] = oH;
    }
}

// ---------------------------------------------------------------------------
// Persistent GRU scan kernel.
// grid = 128 blocks (1/SM guaranteed), 512 threads.
// Block owns JT=8 hidden units (24 gate rows); W slice resident in smem.
// Warp w: ks = w>>3 (K half: 512 k), rg = w&7 (3 gate rows).
// Lane l: batches l and l+32.  f32x2 accumulators over k-parity.
// h streamed in 32k x 64b chunks, double-buffered, per-half named barrier.
// Grid-wide sync per step via release/acquire counter.
// ---------------------------------------------------------------------------
__global__ void __launch_bounds__(512, 1)
gru_persistent(float* __restrict__ out,
               const float* __restrict__ w_hh,
               const float* __restrict__ b_hh)
{
    extern __shared__ __align__(16) float smem[];
    float* Ws  = smem;                          // [24][1024]
    float* Hc  = Ws + NROW * H_SZ;              // [2 ks][2 buf][64][HS]
    float* Red = Hc + 2 * 2 * 64 * HS;          // [2 ks][24][REDS]

    const int tid  = threadIdx.x;
    const int w    = tid >> 5;
    const int lane = tid & 31;
    const int ks   = w >> 3;                    // 0/1 : K half
    const int rg   = w & 7;                     // row group (3 rows)
    const int j0   = blockIdx.x * JT;

    // ---- load W slice into smem (once) ----
    for (int idx = tid; idx < NROW * (H_SZ / 4); idx += 512) {
        int row = idx >> 8;                     // /256
        int q   = idx & 255;
        int g = row >> 3, jj = row & 7;
        *(float4*)&Ws[row * H_SZ + 4 * q] =
            *(const float4*)&w_hh[(size_t)(g * H_SZ + j0 + jj) * H_SZ + 4 * q];
    }

    // ---- epilogue thread mapping + loop-invariant bias ----
    const int eb  = tid >> 3;                   // batch 0..63
    const int ejj = tid & 7;
    const int ej  = j0 + ejj;
    const float bhr = b_hh[ej];
    const float bhz = b_hh[H_SZ + ej];
    const float bhn = b_hh[2 * H_SZ + ej];

    // chunk loader mapping (per half: th 0..255, 2 float4 each)
    const int th  = tid & 255;
    const int lb0 = th >> 3;                    // batch 0..31 (second: +32)
    const int lq0 = th & 7;                     // float4 index within 32k
    const int kbase = ks * 512;

    float* HcH = Hc + ks * (2 * 64 * HS);
    const float* wr0 = &Ws[(rg * 3 + 0) * H_SZ + kbase];
    const float* wr1 = &Ws[(rg * 3 + 1) * H_SZ + kbase];
    const float* wr2 = &Ws[(rg * 3 + 2) * H_SZ + kbase];

    __syncthreads();

    unsigned target = NBLK;
    float* hn_out = out + (size_t)T_LEN * B_SZ * H_SZ;

    #pragma unroll 1
    for (int t = 0; t < T_LEN; t++) {
        const float* hp_base = (t == 0) ? g_h0
                             : out + (size_t)(t - 1) * B_SZ * H_SZ;
        float* ho = out + (size_t)t * B_SZ * H_SZ;

        // epilogue prefetch (xg + h_prev element)
        const float* xg = g_gates + (size_t)t * B_SZ * G3H + (size_t)eb * G3H;
        float xr = xg[ej];
        float xz = xg[H_SZ + ej];
        float xn = xg[2 * H_SZ + ej];
        float hpv = __ldcg(&hp_base[(size_t)eb * H_SZ + ej]);

        ull a00 = 0, a01 = 0, a10 = 0, a11 = 0, a20 = 0, a21 = 0;

        // prefetch + store chunk 0
        float4 r0 = __ldcg((const float4*)&hp_base[(size_t)lb0 * H_SZ + kbase + lq0 * 4]);
        float4 r1 = __ldcg((const float4*)&hp_base[(size_t)(lb0 + 32) * H_SZ + kbase + lq0 * 4]);
        {
            float* d0 = &HcH[lb0 * HS + lq0 * 4];
            float* d1 = &HcH[(lb0 + 32) * HS + lq0 * 4];
            *(float2*)&d0[0] = make_float2(r0.x, r0.y);
            *(float2*)&d0[2] = make_float2(r0.z, r0.w);
            *(float2*)&d1[0] = make_float2(r1.x, r1.y);
            *(float2*)&d1[2] = make_float2(r1.z, r1.w);
        }
        asm volatile("bar.sync %0, 256;" :: "r"(ks + 1) : "memory");

        #pragma unroll 2
        for (int c = 0; c < 16; c++) {
            const int buf = c & 1;
            if (c < 15) {
                int kc = kbase + (c + 1) * 32 + lq0 * 4;
                r0 = __ldcg((const float4*)&hp_base[(size_t)lb0 * H_SZ + kc]);
                r1 = __ldcg((const float4*)&hp_base[(size_t)(lb0 + 32) * H_SZ + kc]);
            }
            const float* ha = &HcH[buf * 64 * HS + lane * HS];        // batch lane
            const float* hb = ha + 32 * HS;                           // batch lane+32
            const float* w0 = wr0 + c * 32;
            const float* w1 = wr1 + c * 32;
            const float* w2 = wr2 + c * 32;
            #pragma unroll
            for (int kp = 0; kp < 16; kp++) {
                ull W0 = *(const ull*)&w0[2 * kp];
                ull W1 = *(const ull*)&w1[2 * kp];
                ull W2 = *(const ull*)&w2[2 * kp];
                ull HA = *(const ull*)&ha[2 * kp];
                ull HB = *(const ull*)&hb[2 * kp];
                ffma2(a00, HA, W0); ffma2(a01, HB, W0);
                ffma2(a10, HA, W1); ffma2(a11, HB, W1);
                ffma2(a20, HA, W2); ffma2(a21, HB, W2);
            }
            if (c < 15) {
                const int nb = buf ^ 1;
                float* d0 = &HcH[nb * 64 * HS + lb0 * HS + lq0 * 4];
                float* d1 = &HcH[nb * 64 * HS + (lb0 + 32) * HS + lq0 * 4];
                *(float2*)&d0[0] = make_float2(r0.x, r0.y);
                *(float2*)&d0[2] = make_float2(r0.z, r0.w);
                *(float2*)&d1[0] = make_float2(r1.x, r1.y);
                *(float2*)&d1[2] = make_float2(r1.z, r1.w);
            }
            asm volatile("bar.sync %0, 256;" :: "r"(ks + 1) : "memory");
        }

        // partials -> Red[ks][row][b]: a*0 = batch lane, a*1 = batch lane+32
        {
            float* R = Red + (size_t)(ks * NROW + rg * 3) * REDS + lane;
            R[0]            = sum2(a00); R[32]            = sum2(a01);
            R[REDS]         = sum2(a10); R[REDS + 32]     = sum2(a11);
            R[2 * REDS]     = sum2(a20); R[2 * REDS + 32] = sum2(a21);
        }
        __syncthreads();

        // fused gate epilogue: one output per thread
        {
            const float* R0 = Red;
            const float* R1 = Red + NROW * REDS;
            float sr = R0[(0 * 8 + ejj) * REDS + eb] + R1[(0 * 8 + ejj) * REDS + eb];
            float sz = R0[(1 * 8 + ejj) * REDS + eb] + R1[(1 * 8 + ejj) * REDS + eb];
            float sn = R0[(2 * 8 + ejj) * REDS + eb] + R1[(2 * 8 + ejj) * REDS + eb];
            float r = 1.f / (1.f + expf(-(xr + sr + bhr)));
            float z = 1.f / (1.f + expf(-(xz + sz + bhz)));
            float n = tanhf(xn + r * (sn + bhn));
            float hnew = (1.f - z) * n + z * hpv;
            __stcg(&ho[(size_t)eb * H_SZ + ej], hnew);
            if (t == T_LEN - 1)
                __stcg(&hn_out[(size_t)eb * H_SZ + ej], hnew);
        }

        // ---- grid-wide sync ----
        __threadfence();
        __syncthreads();
        if (tid == 0) {
            asm volatile("red.release.gpu.global.add.u32 [%0], %1;"
                         :: "l"(&g_sync), "r"(1u) : "memory");
            unsigned v;
            do {
                asm volatile("ld.acquire.gpu.global.u32 %0, [%1];"
                             : "=r"(v) : "l"(&g_sync) : "memory");
            } while (v < target);
        }
        __syncthreads();
        target += NBLK;
    }
}

extern "C" void kernel_launch(void* const* d_in, const int* in_sizes, int n_in,
                              void* d_out, int out_size)
{
    const float* x    = (const float*)d_in[0];   // (T, B, I)
    const float* w_ih = (const float*)d_in[1];   // (3H, I)
    const float* w_hh = (const float*)d_in[2];   // (3H, H)
    const float* b_ih = (const float*)d_in[3];   // (3H,)
    const float* b_hh = (const float*)d_in[4];   // (3H,)
    float* out = (float*)d_out;

    // reset the grid-sync counter (graph-capturable H2D memcpy)
    static unsigned h_zero = 0;
    void* sync_addr = nullptr;
    cudaGetSymbolAddress(&sync_addr, g_sync);
    cudaMemcpyAsync(sync_addr, &h_zero, sizeof(unsigned),
                    cudaMemcpyHostToDevice, 0);

    // Phase 1: input projection GEMM
    dim3 gridA(G3H / 64, M_TOT / 128);
    gemm_xgates<<<gridA, 256>>>(x, w_ih, b_ih);

    // Phase 2: persistent recurrent scan (all 512 steps in one kernel)
    const int smem_bytes = (NROW * H_SZ + 2 * 2 * 64 * HS + 2 * NROW * REDS)
                           * (int)sizeof(float);
    cudaFuncSetAttribute(gru_persistent,
                         cudaFuncAttributeMaxDynamicSharedMemorySize, smem_bytes);
    gru_persistent<<<NBLK, 512, smem_bytes>>>(out, w_hh, b_hh);
}

// round 6
// speedup vs baseline: 2.5624x; 1.1279x over previous
#include <cuda_runtime.h>
#include <math.h>

// Problem constants
#define T_LEN 512
#define B_SZ  64
#define I_SZ  512
#define H_SZ  1024
#define G3H   3072
#define M_TOT 32768          // T*B

#define NBLK  128            // persistent blocks (1 per SM)
#define JT    8              // hidden units per block
#define NROW  24             // gate rows per block (3*JT)
#define KSN   4              // k-slices
#define RGN   4              // row groups (6 rows each)
#define KW    256            // k per slice
#define HS2   36             // h chunk stride (16B-aligned float4)
#define REDS  66

typedef unsigned long long ull;

__device__ __align__(16) float g_gates[(size_t)M_TOT * G3H];
__device__ __align__(16) float g_h0[B_SZ * H_SZ];  // zero-init, never written
__device__ unsigned g_sync;

// ---------------------------------------------------------------------------
// f32x2 helpers
// ---------------------------------------------------------------------------
__device__ __forceinline__ void ffma2(ull& d, ull a, ull b) {
    asm("fma.rn.f32x2 %0, %1, %2, %0;" : "+l"(d) : "l"(a), "l"(b));
}
__device__ __forceinline__ float sum2(ull v) {
    float lo, hi;
    asm("mov.b64 {%0, %1}, %2;" : "=f"(lo), "=f"(hi) : "l"(v));
    return lo + hi;
}
__device__ __forceinline__ void unpack2(ull v, float& lo, float& hi) {
    asm("mov.b64 {%0, %1}, %2;" : "=f"(lo), "=f"(hi) : "l"(v));
}

// ---------------------------------------------------------------------------
// Kernel A: x_gates = x @ w_ih^T + b_ih.  M=32768, N=3072, K=512.
// 128x128 tile, K-tile 8, 256 threads, thread tile 8m x 8n.
// f32x2 packs n-parity; A operand pre-duplicated in smem.
// ---------------------------------------------------------------------------
__global__ __launch_bounds__(256)
void gemm_xgates(const float* __restrict__ A,
                 const float* __restrict__ W,
                 const float* __restrict__ bias)
{
    __shared__ __align__(16) float As2[2][8][258];  // [kk][m*2 + dup]
    __shared__ __align__(16) float Bs[2][8][132];   // [kk][n]

    const int m0 = blockIdx.y * 128;
    const int n0 = blockIdx.x * 128;
    const int tid = threadIdx.x;
    const int tm = tid >> 4;          // 0..15 -> rows tm*8..+7
    const int tn = tid & 15;          // 0..15 -> cols tn*8..+7
    const int lr = tid >> 1;          // 0..127
    const int lk4 = (tid & 1) * 4;    // 0 or 4

    ull acc[8][4];
    #pragma unroll
    for (int i = 0; i < 8; i++)
        #pragma unroll
        for (int p = 0; p < 4; p++) acc[i][p] = 0ull;

    float4 av = *(const float4*)&A[(size_t)(m0 + lr) * I_SZ + lk4];
    float4 wv = *(const float4*)&W[(size_t)(n0 + lr) * I_SZ + lk4];
    {
        As2[0][lk4 + 0][lr * 2] = av.x; As2[0][lk4 + 0][lr * 2 + 1] = av.x;
        As2[0][lk4 + 1][lr * 2] = av.y; As2[0][lk4 + 1][lr * 2 + 1] = av.y;
        As2[0][lk4 + 2][lr * 2] = av.z; As2[0][lk4 + 2][lr * 2 + 1] = av.z;
        As2[0][lk4 + 3][lr * 2] = av.w; As2[0][lk4 + 3][lr * 2 + 1] = av.w;
        Bs[0][lk4 + 0][lr] = wv.x; Bs[0][lk4 + 1][lr] = wv.y;
        Bs[0][lk4 + 2][lr] = wv.z; Bs[0][lk4 + 3][lr] = wv.w;
    }
    __syncthreads();

    #pragma unroll 1
    for (int kt = 0; kt < 64; kt++) {
        const int buf = kt & 1;
        if (kt < 63) {
            int k0 = (kt + 1) * 8 + lk4;
            av = *(const float4*)&A[(size_t)(m0 + lr) * I_SZ + k0];
            wv = *(const float4*)&W[(size_t)(n0 + lr) * I_SZ + k0];
        }
        #pragma unroll
        for (int kk = 0; kk < 8; kk++) {
            ull am[8];
            #pragma unroll
            for (int i = 0; i < 8; i++)
                am[i] = *(const ull*)&As2[buf][kk][(tm * 8 + i) * 2];
            ulonglong2 b0 = *(const ulonglong2*)&Bs[buf][kk][tn * 8];
            ulonglong2 b1 = *(const ulonglong2*)&Bs[buf][kk][tn * 8 + 4];
            #pragma unroll
            for (int i = 0; i < 8; i++) {
                ffma2(acc[i][0], am[i], b0.x);
                ffma2(acc[i][1], am[i], b0.y);
                ffma2(acc[i][2], am[i], b1.x);
                ffma2(acc[i][3], am[i], b1.y);
            }
        }
        if (kt < 63) {
            const int nb = buf ^ 1;
            As2[nb][lk4 + 0][lr * 2] = av.x; As2[nb][lk4 + 0][lr * 2 + 1] = av.x;
            As2[nb][lk4 + 1][lr * 2] = av.y; As2[nb][lk4 + 1][lr * 2 + 1] = av.y;
            As2[nb][lk4 + 2][lr * 2] = av.z; As2[nb][lk4 + 2][lr * 2 + 1] = av.z;
            As2[nb][lk4 + 3][lr * 2] = av.w; As2[nb][lk4 + 3][lr * 2 + 1] = av.w;
            Bs[nb][lk4 + 0][lr] = wv.x; Bs[nb][lk4 + 1][lr] = wv.y;
            Bs[nb][lk4 + 2][lr] = wv.z; Bs[nb][lk4 + 3][lr] = wv.w;
        }
        __syncthreads();
    }

    const int nn = n0 + tn * 8;
    float4 bv0 = *(const float4*)&bias[nn];
    float4 bv1 = *(const float4*)&bias[nn + 4];
    #pragma unroll
    for (int i = 0; i < 8; i++) {
        float c0, c1, c2, c3, c4, c5, c6, c7;
        unpack2(acc[i][0], c0, c1);
        unpack2(acc[i][1], c2, c3);
        unpack2(acc[i][2], c4, c5);
        unpack2(acc[i][3], c6, c7);
        float4 o0 = make_float4(c0 + bv0.x, c1 + bv0.y, c2 + bv0.z, c3 + bv0.w);
        float4 o1 = make_float4(c4 + bv1.x, c5 + bv1.y, c6 + bv1.z, c7 + bv1.w);
        int row = m0 + tm * 8 + i;
        *(float4*)&g_gates[(size_t)row * G3H + nn]     = o0;
        *(float4*)&g_gates[(size_t)row * G3H + nn + 4] = o1;
    }
}

// ---------------------------------------------------------------------------
// Persistent GRU scan kernel.
// grid = 128 blocks (1/SM), 512 threads = 16 warps.
// Warp w: ks = w&3 (256-k slice), rg = w>>2 (6 gate rows).
// W slice resident in smem (96KB); W read as broadcast LDS.128.
// h streamed per ks-group in 32-k double-buffered chunks (stride 36).
// Lane l: batches l and l+32; f32x2 accumulators over k-parity.
// 24 FFMA2 per 8 LDS-phase unit -> near fma-bound.
// ---------------------------------------------------------------------------
__global__ void __launch_bounds__(512, 1)
gru_persistent(float* __restrict__ out,
               const float* __restrict__ w_hh,
               const float* __restrict__ b_hh)
{
    extern __shared__ __align__(16) float smem[];
    float* Ws  = smem;                          // [24][1024]
    float* Hw  = Ws + NROW * H_SZ;              // [4 ks][2 buf][64][HS2]
    float* Red = Hw + KSN * 2 * 64 * HS2;       // [4 ks][24][REDS]

    const int tid  = threadIdx.x;
    const int w    = tid >> 5;
    const int lane = tid & 31;
    const int ks   = w & 3;
    const int rg   = w >> 2;
    const int j0   = blockIdx.x * JT;

    // ---- load W slice into smem (once); row = g*8 + jj ----
    for (int idx = tid; idx < NROW * (H_SZ / 4); idx += 512) {
        int row = idx >> 8;
        int q   = idx & 255;
        int g = row >> 3, jj = row & 7;
        *(float4*)&Ws[row * H_SZ + 4 * q] =
            *(const float4*)&w_hh[(size_t)(g * H_SZ + j0 + jj) * H_SZ + 4 * q];
    }

    // ---- epilogue mapping ----
    const int eb  = tid >> 3;                   // batch 0..63
    const int ejj = tid & 7;
    const int ej  = j0 + ejj;
    const float bhr = b_hh[ej];
    const float bhz = b_hh[H_SZ + ej];
    const float bhn = b_hh[2 * H_SZ + ej];

    // ---- chunk loader mapping (per ks group of 128 threads) ----
    const int gtid = rg * 32 + lane;            // 0..127 within ks group
    const int lb0  = gtid >> 3;                 // 0..15 (batches lb0+16i)
    const int lq   = gtid & 7;                  // float4 index in 32k chunk
    const int kofs = ks * KW;

    float* HwKs = Hw + ks * (2 * 64 * HS2);
    const float* wp[6];
    #pragma unroll
    for (int i = 0; i < 6; i++)
        wp[i] = &Ws[(rg * 6 + i) * H_SZ + kofs];

    __syncthreads();

    unsigned target = NBLK;
    float* hn_out = out + (size_t)T_LEN * B_SZ * H_SZ;
    float hpv = 0.f;

    #pragma unroll 1
    for (int t = 0; t < T_LEN; t++) {
        const float* hp = (t == 0) ? g_h0
                        : out + (size_t)(t - 1) * B_SZ * H_SZ;
        float* ho = out + (size_t)t * B_SZ * H_SZ;

        const float* xg = g_gates + (size_t)t * B_SZ * G3H + (size_t)eb * G3H;
        float xr = __ldcg(&xg[ej]);
        float xz = __ldcg(&xg[H_SZ + ej]);
        float xn = __ldcg(&xg[2 * H_SZ + ej]);

        ull acc[6][2];
        #pragma unroll
        for (int i = 0; i < 6; i++) { acc[i][0] = 0ull; acc[i][1] = 0ull; }

        float4 r4[4];
        // prefetch + store chunk 0
        #pragma unroll
        for (int i = 0; i < 4; i++)
            r4[i] = __ldcg((const float4*)&hp[(size_t)(lb0 + 16 * i) * H_SZ + kofs + lq * 4]);
        #pragma unroll
        for (int i = 0; i < 4; i++)
            *(float4*)&HwKs[(size_t)(lb0 + 16 * i) * HS2 + lq * 4] = r4[i];
        asm volatile("bar.sync %0, 128;" :: "r"(ks + 1) : "memory");

        #pragma unroll 1
        for (int c = 0; c < 8; c++) {
            const int buf = c & 1;
            if (c < 7) {
                int kc = kofs + (c + 1) * 32 + lq * 4;
                #pragma unroll
                for (int i = 0; i < 4; i++)
                    r4[i] = __ldcg((const float4*)&hp[(size_t)(lb0 + 16 * i) * H_SZ + kc]);
            }
            const float* hbA = &HwKs[(size_t)(buf * 64 + lane) * HS2];
            const float* hbB = hbA + 32 * HS2;
            #pragma unroll
            for (int u = 0; u < 8; u++) {
                ulonglong2 hA = *(const ulonglong2*)&hbA[u * 4];
                ulonglong2 hB = *(const ulonglong2*)&hbB[u * 4];
                #pragma unroll
                for (int i = 0; i < 6; i++) {
                    ulonglong2 wv = *(const ulonglong2*)&wp[i][c * 32 + u * 4];
                    ffma2(acc[i][0], hA.x, wv.x);
                    ffma2(acc[i][0], hA.y, wv.y);
                    ffma2(acc[i][1], hB.x, wv.x);
                    ffma2(acc[i][1], hB.y, wv.y);
                }
            }
            if (c < 7) {
                const int nb = buf ^ 1;
                #pragma unroll
                for (int i = 0; i < 4; i++)
                    *(float4*)&HwKs[(size_t)(nb * 64 + lb0 + 16 * i) * HS2 + lq * 4] = r4[i];
            }
            asm volatile("bar.sync %0, 128;" :: "r"(ks + 1) : "memory");
        }

        // partials -> Red[ks][row][b]
        #pragma unroll
        for (int i = 0; i < 6; i++) {
            float* R = Red + (size_t)(ks * NROW + rg * 6 + i) * REDS;
            R[lane]      = sum2(acc[i][0]);
            R[lane + 32] = sum2(acc[i][1]);
        }
        __syncthreads();

        // fused gate epilogue: one output per thread
        {
            float sr = 0.f, sz = 0.f, sn = 0.f;
            #pragma unroll
            for (int s = 0; s < KSN; s++) {
                const float* R = Red + (size_t)s * NROW * REDS;
                sr += R[(0 * 8 + ejj) * REDS + eb];
                sz += R[(1 * 8 + ejj) * REDS + eb];
                sn += R[(2 * 8 + ejj) * REDS + eb];
            }
            float r = 1.f / (1.f + expf(-(xr + sr + bhr)));
            float z = 1.f / (1.f + expf(-(xz + sz + bhz)));
            float n = tanhf(xn + r * (sn + bhn));
            float hnew = (1.f - z) * n + z * hpv;
            __stcg(&ho[(size_t)eb * H_SZ + ej], hnew);
            if (t == T_LEN - 1)
                __stcg(&hn_out[(size_t)eb * H_SZ + ej], hnew);
            hpv = hnew;
        }

        // ---- grid-wide sync ----
        __threadfence();
        __syncthreads();
        if (tid == 0) {
            asm volatile("red.release.gpu.global.add.u32 [%0], %1;"
                         :: "l"(&g_sync), "r"(1u) : "memory");
            unsigned v;
            do {
                asm volatile("ld.acquire.gpu.global.u32 %0, [%1];"
                             : "=r"(v) : "l"(&g_sync) : "memory");
            } while (v < target);
        }
        __syncthreads();
        target += NBLK;
    }
}

extern "C" void kernel_launch(void* const* d_in, const int* in_sizes, int n_in,
                              void* d_out, int out_size)
{
    const float* x    = (const float*)d_in[0];   // (T, B, I)
    const float* w_ih = (const float*)d_in[1];   // (3H, I)
    const float* w_hh = (const float*)d_in[2];   // (3H, H)
    const float* b_ih = (const float*)d_in[3];   // (3H,)
    const float* b_hh = (const float*)d_in[4];   // (3H,)
    float* out = (float*)d_out;

    // reset the grid-sync counter (graph-capturable H2D memcpy)
    static unsigned h_zero = 0;
    void* sync_addr = nullptr;
    cudaGetSymbolAddress(&sync_addr, g_sync);
    cudaMemcpyAsync(sync_addr, &h_zero, sizeof(unsigned),
                    cudaMemcpyHostToDevice, 0);

    // Phase 1: input projection GEMM
    dim3 gridA(G3H / 128, M_TOT / 128);
    gemm_xgates<<<gridA, 256>>>(x, w_ih, b_ih);

    // Phase 2: persistent recurrent scan (all 512 steps in one kernel)
    const int smem_bytes = (NROW * H_SZ + KSN * 2 * 64 * HS2 + KSN * NROW * REDS)
                           * (int)sizeof(float);
    cudaFuncSetAttribute(gru_persistent,
                         cudaFuncAttributeMaxDynamicSharedMemorySize, smem_bytes);
    gru_persistent<<<NBLK, 512, smem_bytes>>>(out, w_hh, b_hh);
}

// round 7
// speedup vs baseline: 2.6250x; 1.0244x over previous
#include <cuda_runtime.h>
#include <math.h>

// Problem constants
#define T_LEN 512
#define B_SZ  64
#define I_SZ  512
#define H_SZ  1024
#define G3H   3072
#define M_TOT 32768          // T*B

#define NBLK  128            // persistent blocks (1 per SM)
#define JT    8              // hidden units per block
#define NROW  24             // gate rows per block (3*JT)
#define KSL   128            // k-slice per warp
#define CHK   16             // k per chunk
#define HST   20             // h window stride (floats; 80B, 16B-aligned, conflict-free)
#define REDS  66

typedef unsigned long long ull;

__device__ __align__(16) float g_gates[(size_t)M_TOT * G3H];
__device__ __align__(16) float g_h0[B_SZ * H_SZ];  // zero-init, never written
__device__ unsigned g_sync;

// ---------------------------------------------------------------------------
// f32x2 helpers
// ---------------------------------------------------------------------------
__device__ __forceinline__ ull dup2(float w) {
    ull r; asm("mov.b64 %0, {%1, %1};" : "=l"(r) : "f"(w)); return r;
}
__device__ __forceinline__ void ffma2(ull& d, ull a, ull b) {
    asm("fma.rn.f32x2 %0, %1, %2, %0;" : "+l"(d) : "l"(a), "l"(b));
}
__device__ __forceinline__ float sum2(ull v) {
    float lo, hi;
    asm("mov.b64 {%0, %1}, %2;" : "=f"(lo), "=f"(hi) : "l"(v));
    return lo + hi;
}
__device__ __forceinline__ void unpack2(ull v, float& lo, float& hi) {
    asm("mov.b64 {%0, %1}, %2;" : "=f"(lo), "=f"(hi) : "l"(v));
}

// ---------------------------------------------------------------------------
// Kernel A: x_gates = x @ w_ih^T + b_ih.  M=32768, N=3072, K=512.
// 128x128 tile, K-tile 8, 256 threads, thread tile 8m x 8n.
// A un-duplicated in smem (dup to f32x2 in regs); B plain, n-parity packed.
// ---------------------------------------------------------------------------
__global__ __launch_bounds__(256)
void gemm_xgates(const float* __restrict__ A,
                 const float* __restrict__ W,
                 const float* __restrict__ bias)
{
    __shared__ __align__(16) float As[2][8][132];   // [kk][m]
    __shared__ __align__(16) float Bs[2][8][132];   // [kk][n]

    const int m0 = blockIdx.y * 128;
    const int n0 = blockIdx.x * 128;
    const int tid = threadIdx.x;
    const int tm = tid >> 4;          // 0..15 -> rows tm*8..+7
    const int tn = tid & 15;          // 0..15 -> cols tn*8..+7
    const int lr = tid >> 1;          // 0..127
    const int lk4 = (tid & 1) * 4;    // 0 or 4

    ull acc[8][4];
    #pragma unroll
    for (int i = 0; i < 8; i++)
        #pragma unroll
        for (int p = 0; p < 4; p++) acc[i][p] = 0ull;

    float4 av = *(const float4*)&A[(size_t)(m0 + lr) * I_SZ + lk4];
    float4 wv = *(const float4*)&W[(size_t)(n0 + lr) * I_SZ + lk4];
    {
        As[0][lk4 + 0][lr] = av.x; As[0][lk4 + 1][lr] = av.y;
        As[0][lk4 + 2][lr] = av.z; As[0][lk4 + 3][lr] = av.w;
        Bs[0][lk4 + 0][lr] = wv.x; Bs[0][lk4 + 1][lr] = wv.y;
        Bs[0][lk4 + 2][lr] = wv.z; Bs[0][lk4 + 3][lr] = wv.w;
    }
    __syncthreads();

    #pragma unroll 1
    for (int kt = 0; kt < 64; kt++) {
        const int buf = kt & 1;
        if (kt < 63) {
            int k0 = (kt + 1) * 8 + lk4;
            av = *(const float4*)&A[(size_t)(m0 + lr) * I_SZ + k0];
            wv = *(const float4*)&W[(size_t)(n0 + lr) * I_SZ + k0];
        }
        #pragma unroll
        for (int kk = 0; kk < 8; kk++) {
            float4 a0 = *(const float4*)&As[buf][kk][tm * 8];
            float4 a1 = *(const float4*)&As[buf][kk][tm * 8 + 4];
            ull am[8];
            am[0] = dup2(a0.x); am[1] = dup2(a0.y);
            am[2] = dup2(a0.z); am[3] = dup2(a0.w);
            am[4] = dup2(a1.x); am[5] = dup2(a1.y);
            am[6] = dup2(a1.z); am[7] = dup2(a1.w);
            ulonglong2 b0 = *(const ulonglong2*)&Bs[buf][kk][tn * 8];
            ulonglong2 b1 = *(const ulonglong2*)&Bs[buf][kk][tn * 8 + 4];
            #pragma unroll
            for (int i = 0; i < 8; i++) {
                ffma2(acc[i][0], am[i], b0.x);
                ffma2(acc[i][1], am[i], b0.y);
                ffma2(acc[i][2], am[i], b1.x);
                ffma2(acc[i][3], am[i], b1.y);
            }
        }
        if (kt < 63) {
            const int nb = buf ^ 1;
            As[nb][lk4 + 0][lr] = av.x; As[nb][lk4 + 1][lr] = av.y;
            As[nb][lk4 + 2][lr] = av.z; As[nb][lk4 + 3][lr] = av.w;
            Bs[nb][lk4 + 0][lr] = wv.x; Bs[nb][lk4 + 1][lr] = wv.y;
            Bs[nb][lk4 + 2][lr] = wv.z; Bs[nb][lk4 + 3][lr] = wv.w;
        }
        __syncthreads();
    }

    const int nn = n0 + tn * 8;
    float4 bv0 = *(const float4*)&bias[nn];
    float4 bv1 = *(const float4*)&bias[nn + 4];
    #pragma unroll
    for (int i = 0; i < 8; i++) {
        float c0, c1, c2, c3, c4, c5, c6, c7;
        unpack2(acc[i][0], c0, c1);
        unpack2(acc[i][1], c2, c3);
        unpack2(acc[i][2], c4, c5);
        unpack2(acc[i][3], c6, c7);
        float4 o0 = make_float4(c0 + bv0.x, c1 + bv0.y, c2 + bv0.z, c3 + bv0.w);
        float4 o1 = make_float4(c4 + bv1.x, c5 + bv1.y, c6 + bv1.z, c7 + bv1.w);
        int row = m0 + tm * 8 + i;
        *(float4*)&g_gates[(size_t)row * G3H + nn]     = o0;
        *(float4*)&g_gates[(size_t)row * G3H + nn + 4] = o1;
    }
}

// ---------------------------------------------------------------------------
// Persistent GRU scan kernel.
// grid = 128 blocks (1/SM), 256 threads = 8 warps.
// Warp w owns k-slice [w*128, w*128+128) and ALL 24 gate rows.
// W slice resident in smem (96KB), broadcast LDS.128.
// Each warp loads + consumes its own h window -> only __syncwarp in mainloop.
// Lane l: batches l and l+32; 48 f32x2 accumulators (24 rows x 2 batches).
// Per 4-k unit: 2 h LDS.128 + 24 W broadcast per 96 FFMA2 -> fma-bound.
// ---------------------------------------------------------------------------
__global__ void __launch_bounds__(256, 1)
gru_persistent(float* __restrict__ out,
               const float* __restrict__ w_hh,
               const float* __restrict__ b_hh)
{
    extern __shared__ __align__(16) float smem[];
    float* Ws  = smem;                          // [24][1024]
    float* Hw  = Ws + NROW * H_SZ;              // [8 w][2 buf][64][HST]
    float* Red = Hw + 8 * 2 * 64 * HST;         // [8 w][24][REDS]

    const int tid  = threadIdx.x;
    const int w    = tid >> 5;
    const int lane = tid & 31;
    const int j0   = blockIdx.x * JT;
    const int kofs = w * KSL;

    // ---- load W slice into smem (once); row = g*8 + jj ----
    for (int idx = tid; idx < NROW * (H_SZ / 4); idx += 256) {
        int row = idx >> 8;
        int q   = idx & 255;
        int g = row >> 3, jj = row & 7;
        *(float4*)&Ws[row * H_SZ + 4 * q] =
            *(const float4*)&w_hh[(size_t)(g * H_SZ + j0 + jj) * H_SZ + 4 * q];
    }

    // ---- epilogue mapping: outputs o = tid, tid+256 ----
    float bh[2][3];
    #pragma unroll
    for (int e = 0; e < 2; e++) {
        int o = tid + e * 256;
        int ej = j0 + (o & 7);
        bh[e][0] = b_hh[ej];
        bh[e][1] = b_hh[H_SZ + ej];
        bh[e][2] = b_hh[2 * H_SZ + ej];
    }

    // ---- loader mapping: lane -> 8 rows (lb + 8i), k-quad lq ----
    const int lb = lane >> 2;                   // 0..7
    const int lq = lane & 3;                    // 0..3
    float* HwW = Hw + w * (2 * 64 * HST);

    __syncthreads();

    unsigned target = NBLK;
    float* hn_out = out + (size_t)T_LEN * B_SZ * H_SZ;
    float hpv[2] = {0.f, 0.f};

    #pragma unroll 1
    for (int t = 0; t < T_LEN; t++) {
        const float* hp = (t == 0) ? g_h0
                        : out + (size_t)(t - 1) * B_SZ * H_SZ;
        float* ho = out + (size_t)t * B_SZ * H_SZ;

        // epilogue x-gate prefetch (streams from DRAM, hidden by mainloop)
        float xr[2], xz[2], xn[2];
        #pragma unroll
        for (int e = 0; e < 2; e++) {
            int o = tid + e * 256;
            const float* xg = g_gates + (size_t)t * B_SZ * G3H
                            + (size_t)(o >> 3) * G3H + j0 + (o & 7);
            xr[e] = __ldcg(&xg[0]);
            xz[e] = __ldcg(&xg[H_SZ]);
            xn[e] = __ldcg(&xg[2 * H_SZ]);
        }

        ull acc[NROW][2];
        #pragma unroll
        for (int i = 0; i < NROW; i++) { acc[i][0] = 0ull; acc[i][1] = 0ull; }

        // chunk 0: load + stage
        float4 r4[8];
        #pragma unroll
        for (int i = 0; i < 8; i++)
            r4[i] = __ldcg((const float4*)&hp[(size_t)(lb + 8 * i) * H_SZ + kofs + lq * 4]);
        #pragma unroll
        for (int i = 0; i < 8; i++)
            *(float4*)&HwW[(lb + 8 * i) * HST + lq * 4] = r4[i];
        __syncwarp();

        #pragma unroll 1
        for (int c = 0; c < 8; c++) {
            const int buf = c & 1;
            if (c < 7) {
                int kc = kofs + (c + 1) * CHK + lq * 4;
                #pragma unroll
                for (int i = 0; i < 8; i++)
                    r4[i] = __ldcg((const float4*)&hp[(size_t)(lb + 8 * i) * H_SZ + kc]);
            }
            const float* hbase = &HwW[buf * 64 * HST];
            const float* wbase = &Ws[kofs + c * CHK];
            #pragma unroll
            for (int u = 0; u < CHK / 4; u++) {
                ulonglong2 hA = *(const ulonglong2*)&hbase[lane * HST + u * 4];
                ulonglong2 hB = *(const ulonglong2*)&hbase[(lane + 32) * HST + u * 4];
                #pragma unroll
                for (int row = 0; row < NROW; row++) {
                    ulonglong2 wv = *(const ulonglong2*)&wbase[row * H_SZ + u * 4];
                    ffma2(acc[row][0], hA.x, wv.x);
                    ffma2(acc[row][0], hA.y, wv.y);
                    ffma2(acc[row][1], hB.x, wv.x);
                    ffma2(acc[row][1], hB.y, wv.y);
                }
            }
            if (c < 7) {
                const int nb = buf ^ 1;
                #pragma unroll
                for (int i = 0; i < 8; i++)
                    *(float4*)&HwW[(nb * 64 + lb + 8 * i) * HST + lq * 4] = r4[i];
            }
            __syncwarp();
        }

        // partials -> Red[w][row][b]
        #pragma unroll
        for (int row = 0; row < NROW; row++) {
            float* R = Red + (size_t)(w * NROW + row) * REDS;
            R[lane]      = sum2(acc[row][0]);
            R[lane + 32] = sum2(acc[row][1]);
        }
        __syncthreads();

        // fused gate epilogue: 2 outputs per thread
        #pragma unroll
        for (int e = 0; e < 2; e++) {
            int o   = tid + e * 256;
            int eb  = o >> 3;
            int ejj = o & 7;
            float sr = 0.f, sz = 0.f, sn = 0.f;
            #pragma unroll
            for (int s = 0; s < 8; s++) {
                const float* R = Red + (size_t)s * NROW * REDS;
                sr += R[(0 * 8 + ejj) * REDS + eb];
                sz += R[(1 * 8 + ejj) * REDS + eb];
                sn += R[(2 * 8 + ejj) * REDS + eb];
            }
            float r = 1.f / (1.f + expf(-(xr[e] + sr + bh[e][0])));
            float z = 1.f / (1.f + expf(-(xz[e] + sz + bh[e][1])));
            float n = tanhf(xn[e] + r * (sn + bh[e][2]));
            float hnew = (1.f - z) * n + z * hpv[e];
            __stcg(&ho[(size_t)eb * H_SZ + j0 + ejj], hnew);
            if (t == T_LEN - 1)
                __stcg(&hn_out[(size_t)eb * H_SZ + j0 + ejj], hnew);
            hpv[e] = hnew;
        }

        // ---- grid-wide sync ----
        __threadfence();
        __syncthreads();
        if (tid == 0) {
            asm volatile("red.release.gpu.global.add.u32 [%0], %1;"
                         :: "l"(&g_sync), "r"(1u) : "memory");
            unsigned v;
            do {
                asm volatile("ld.acquire.gpu.global.u32 %0, [%1];"
                             : "=r"(v) : "l"(&g_sync) : "memory");
            } while (v < target);
        }
        __syncthreads();
        target += NBLK;
    }
}

extern "C" void kernel_launch(void* const* d_in, const int* in_sizes, int n_in,
                              void* d_out, int out_size)
{
    const float* x    = (const float*)d_in[0];   // (T, B, I)
    const float* w_ih = (const float*)d_in[1];   // (3H, I)
    const float* w_hh = (const float*)d_in[2];   // (3H, H)
    const float* b_ih = (const float*)d_in[3];   // (3H,)
    const float* b_hh = (const float*)d_in[4];   // (3H,)
    float* out = (float*)d_out;

    // reset the grid-sync counter (graph-capturable H2D memcpy)
    static unsigned h_zero = 0;
    void* sync_addr = nullptr;
    cudaGetSymbolAddress(&sync_addr, g_sync);
    cudaMemcpyAsync(sync_addr, &h_zero, sizeof(unsigned),
                    cudaMemcpyHostToDevice, 0);

    // Phase 1: input projection GEMM
    dim3 gridA(G3H / 128, M_TOT / 128);
    gemm_xgates<<<gridA, 256>>>(x, w_ih, b_ih);

    // Phase 2: persistent recurrent scan (all 512 steps in one kernel)
    const int smem_bytes = (NROW * H_SZ + 8 * 2 * 64 * HST + 8 * NROW * REDS)
                           * (int)sizeof(float);
    cudaFuncSetAttribute(gru_persistent,
                         cudaFuncAttributeMaxDynamicSharedMemorySize, smem_bytes);
    gru_persistent<<<NBLK, 256, smem_bytes>>>(out, w_hh, b_hh);
}